// round 17
// baseline (speedup 1.0000x reference)
#include <cuda_runtime.h>
#include <cuda_bf16.h>
#include <cstdint>

// Focal BCE with logits, mean-reduced. TERMINAL KERNEL (R14, 53.28us).
//   loss(x,t) = a * (1-q)^gamma * (-ln q),  q = sigmoid((t==1)? x : -x),
//               a = (t==1)? ALPHA : 1-ALPHA
// Base-2 formulation (ln2 folded into alpha):
//   u   = 2^(-log2e * y)             (= e^-y)
//   spl = log2(1 + u)                (= -ln(q)/ln2)
//   w   = 2^(-g*log2e*y - g*spl)     (= (1-q)^gamma)
//   loss = (a*ln2) * w * spl
// => 3 MUFU + ~5 FP ops per element; fully hidden under the memory stream.
//
// Why this is terminal: effective bandwidth is 6.30 TB/s across every
// measured variant (tiles 512/1024/2048 elem, 128b and 256b loads), matching
// the chip-wide LTS throughput cap (~6300 B/cyc, path-independent: LDG.cv
// == TMA). All SM pipes <=56%; occupancy, MLP, and last-wave quantization
// were each individually falsified as limiters (R7/R9/R12/R14). Input
// traffic (335.5 MB) is irreducible.
//
// Structure:
//  - Flat de-tailed schedule: 2048 elements/CTA, 20480 CTAs, HW
//    work-distributor backfill (~1us quantum) -> no static-wave tail (-3.3us
//    vs one-wave persistent grid, R7).
//  - LDG.E.256 (sm_100a ld.global.nc.v8): one 32B logits + one 32B target
//    load per thread.
//  - Single-launch reduction, no gpu-scope fence (CCTL.IVALL L1-flush
//    measured ~1us, R4): relaxed atomicAdd partials into g_sum;
//    atom.acq_rel.inc counter (self-wraps at gridDim.x ->
//    graph-replay-deterministic); last block ld.acquire's g_sum, writes
//    d_out, relaxed-resets g_sum.

#define FOCAL_GAMMA 0.2f
#define FOCAL_ALPHA 0.6f
#define LOG2E 1.4426950408889634f
#define LN2   0.6931471805599453f

#define TILE_ELEMS 2048          // elements per CTA (256 thr x 8)

__device__ float        g_sum   = 0.0f;
__device__ unsigned int g_count = 0;

__device__ __forceinline__ float focal_elem(float x, int t) {
    bool pos = (t == 1);
    float y = pos ? x : -x;
    float a = pos ? (FOCAL_ALPHA * LN2) : ((1.0f - FOCAL_ALPHA) * LN2);
    float u   = exp2f(-LOG2E * y);                       // e^{-y}
    float spl = __log2f(1.0f + u);                       // -ln(q)/ln2
    float w   = exp2f(fmaf(-(FOCAL_GAMMA * LOG2E), y,
                           -FOCAL_GAMMA * spl));         // (1-q)^gamma
    return a * (w * spl);
}

// 256-bit global loads (sm_100a). 32-byte aligned addresses required.
__device__ __forceinline__ void ldg256_f32(const float* p, float r[8]) {
    asm volatile("ld.global.nc.v8.f32 {%0,%1,%2,%3,%4,%5,%6,%7}, [%8];"
                 : "=f"(r[0]), "=f"(r[1]), "=f"(r[2]), "=f"(r[3]),
                   "=f"(r[4]), "=f"(r[5]), "=f"(r[6]), "=f"(r[7])
                 : "l"(p));
}

__device__ __forceinline__ void ldg256_s32(const int* p, int r[8]) {
    asm volatile("ld.global.nc.v8.b32 {%0,%1,%2,%3,%4,%5,%6,%7}, [%8];"
                 : "=r"(r[0]), "=r"(r[1]), "=r"(r[2]), "=r"(r[3]),
                   "=r"(r[4]), "=r"(r[5]), "=r"(r[6]), "=r"(r[7])
                 : "l"(p));
}

__global__ void __launch_bounds__(256)
focal_flat_kernel(const float* __restrict__ x,
                  const int*   __restrict__ t,
                  float* __restrict__ out,
                  long long n_total, float inv_total) {
    int tid = threadIdx.x;
    long long base = (long long)blockIdx.x * TILE_ELEMS + (long long)tid * 8;

    float acc = 0.0f;

    if (base + 8 <= n_total) {
        // Two independent LDG.E.256 issued back-to-back (64B in flight).
        float xv[8];
        int   tv[8];
        ldg256_f32(x + base, xv);
        ldg256_s32(t + base, tv);
        #pragma unroll
        for (int k = 0; k < 8; k++)
            acc += focal_elem(xv[k], tv[k]);
    } else {
        // Boundary chunk: scalar guarded loads.
        #pragma unroll
        for (int k = 0; k < 8; k++) {
            long long j = base + k;
            if (j < n_total)
                acc += focal_elem(x[j], t[j]);
        }
    }

    // Intra-warp reduction
    #pragma unroll
    for (int off = 16; off > 0; off >>= 1)
        acc += __shfl_xor_sync(0xffffffffu, acc, off);

    __shared__ float warp_sums[8];
    int lane = tid & 31;
    int wid  = tid >> 5;
    if (lane == 0) warp_sums[wid] = acc;
    __syncthreads();

    if (wid == 0) {
        acc = (lane < 8) ? warp_sums[lane] : 0.0f;
        #pragma unroll
        for (int off = 4; off > 0; off >>= 1)
            acc += __shfl_xor_sync(0xffffffffu, acc, off);

        if (lane == 0) {
            atomicAdd(&g_sum, acc * inv_total);   // relaxed partial
            unsigned int prev;
            // acq_rel: releases our add before the inc, acquires all
            // prior blocks' adds when we observe the final count.
            asm volatile("atom.acq_rel.gpu.global.inc.u32 %0, [%1], %2;"
                         : "=r"(prev)
                         : "l"(&g_count), "r"(gridDim.x - 1)
                         : "memory");
            if (prev == gridDim.x - 1) {
                float total;
                asm volatile("ld.acquire.gpu.global.f32 %0, [%1];"
                             : "=f"(total) : "l"(&g_sum) : "memory");
                out[0] = total;
                asm volatile("st.relaxed.gpu.global.f32 [%0], %1;"
                             :: "l"(&g_sum), "f"(0.0f) : "memory");
            }
        }
    }
}

extern "C" void kernel_launch(void* const* d_in, const int* in_sizes, int n_in,
                              void* d_out, int out_size) {
    const float* logits = (const float*)d_in[0];
    const int*   target = (const int*)d_in[1];
    float* out = (float*)d_out;

    long long n_total = (long long)in_sizes[0];
    float inv_total = (float)(1.0 / (double)n_total);

    // One CTA per 2048 elements (8 per thread). For N*C = 41.94M: 20480 CTAs.
    long long blocks_ll = (n_total + TILE_ELEMS - 1) / TILE_ELEMS;
    int blocks = (int)blocks_ll;
    if (blocks < 1) blocks = 1;

    focal_flat_kernel<<<blocks, 256>>>(logits, target, out,
                                       n_total, inv_total);
}